// round 4
// baseline (speedup 1.0000x reference)
#include <cuda_runtime.h>
#include <mma.h>
#include <math.h>
#include <stdint.h>

using namespace nvcuda;

#define DIM 128
#define F 64
#define NG 50
#define NMAX 100352

#define TAB_INTERVALS 8192
#define TAB_ROWS (TAB_INTERVALS + 1)
#define TAB_MAXD 13.0f

static __device__ __align__(16) float g_tab[(size_t)TAB_ROWS * F + 64];
static __device__ __align__(16) float g_h1[(size_t)NMAX * F];
static __device__ __align__(16) float g_agg[(size_t)NMAX * F];

__device__ __forceinline__ float sspf(float v) {
    return fmaxf(v, 0.0f) + log1pf(expf(-fabsf(v))) - 0.69314718055994531f;
}
// round fp32 -> tf32-representable fp32 (cvt.rna.tf32 is sm_80+, family-safe)
__device__ __forceinline__ float rtf(float v) {
    uint32_t r;
    asm("cvt.rna.tf32.f32 %0, %1;" : "=r"(r) : "f"(v));
    return __uint_as_float(r);
}

// ===========================================================================
// Kernel 1: dist -> W*C table.  One block (64 threads) per row.
// ===========================================================================
__global__ void table_kernel(const float* __restrict__ w1, const float* __restrict__ b1,
                             const float* __restrict__ w2, const float* __restrict__ b2) {
    __shared__ float gauss[NG];
    __shared__ float hid[F];
    int e = blockIdx.x;
    int f = threadIdx.x;  // 0..63
    float dist = (float)e * (TAB_MAXD / (float)TAB_INTERVALS);

    const float dOff  = 10.0f / 49.0f;
    const float coeff = -0.5f / (dOff * dOff);

    if (f < NG) {
        float d = dist - (float)f * dOff;
        gauss[f] = expf(coeff * d * d);
    }
    __syncthreads();

    float pre = b1[f];
#pragma unroll 1
    for (int i = 0; i < NG; i++) pre = fmaf(gauss[i], w1[i * F + f], pre);
    hid[f] = sspf(pre);
    __syncthreads();

    float o = b2[f];
#pragma unroll 1
    for (int i = 0; i < F; i++) o = fmaf(hid[i], w2[i * F + f], o);

    float C = 0.5f * (cosf(dist * (float)(M_PI / 10.0)) + 1.0f);
    g_tab[(size_t)e * F + f] = o * C;
}

// ===========================================================================
// Kernel 2: zero agg
// ===========================================================================
__global__ void zero_agg_kernel(int n4) {
    int i = blockIdx.x * blockDim.x + threadIdx.x;
    if (i < n4) reinterpret_cast<float4*>(g_agg)[i] = make_float4(0.f, 0.f, 0.f, 0.f);
}

// ===========================================================================
// Kernel 3 (wmma tf32): h1 = x @ conv_lin1_w   [N,128]@[128,64]
// One warp per 16-row strip; all operands straight from global (L1-resident W).
// ===========================================================================
__global__ void __launch_bounds__(256)
gemm1_wmma_kernel(const float* __restrict__ x, const float* __restrict__ w, int N) {
    int gw = blockIdx.x * (blockDim.x >> 5) + (threadIdx.x >> 5);
    int row0 = gw * 16;
    if (row0 >= N) return;

    if (row0 + 16 <= N) {
        wmma::fragment<wmma::accumulator, 16, 16, 8, float> acc[4];
#pragma unroll
        for (int n = 0; n < 4; n++) wmma::fill_fragment(acc[n], 0.0f);

#pragma unroll 4
        for (int k = 0; k < DIM; k += 8) {
            wmma::fragment<wmma::matrix_a, 16, 16, 8, wmma::precision::tf32, wmma::row_major> a;
            wmma::load_matrix_sync(a, x + (size_t)row0 * DIM + k, DIM);
#pragma unroll
            for (int t = 0; t < a.num_elements; t++) a.x[t] = wmma::__float_to_tf32(a.x[t]);
#pragma unroll
            for (int n = 0; n < 4; n++) {
                wmma::fragment<wmma::matrix_b, 16, 16, 8, wmma::precision::tf32, wmma::row_major> b;
                wmma::load_matrix_sync(b, w + (size_t)k * F + n * 16, F);
#pragma unroll
                for (int t = 0; t < b.num_elements; t++) b.x[t] = wmma::__float_to_tf32(b.x[t]);
                wmma::mma_sync(acc[n], a, b, acc[n]);
            }
        }
#pragma unroll
        for (int n = 0; n < 4; n++)
            wmma::store_matrix_sync(g_h1 + (size_t)row0 * F + n * 16, acc[n], F,
                                    wmma::mem_row_major);
    } else {
        // scalar fallback for a trailing partial strip
        int lane = threadIdx.x & 31;
        for (int r = row0; r < N; r++)
            for (int c = lane; c < F; c += 32) {
                float s = 0.f;
                for (int k = 0; k < DIM; k++)
                    s = fmaf(x[(size_t)r * DIM + k], w[(size_t)k * F + c], s);
                g_h1[(size_t)r * F + c] = s;
            }
    }
}

// ===========================================================================
// Kernel 4: edge scatter (int32 indices) — identical to R2-passing version
// ===========================================================================
__global__ void edge_kernel(const int* __restrict__ ei,
                            const float* __restrict__ pos, int E) {
    const float INV_STEP = (float)TAB_INTERVALS / TAB_MAXD;
    int lane = threadIdx.x & 31;
    int sub  = lane & 15;
    long long widx = (long long)blockIdx.x * (blockDim.x >> 5) + (threadIdx.x >> 5);
    long long e = widx * 2 + (lane >> 4);
    bool valid = (e < E);

    int src = 0, dst = 0;
    float t = 0.f;
    if (sub == 0 && valid) {
        src = ei[e];
        dst = ei[E + e];
        float ax = pos[(size_t)src * 3 + 0], ay = pos[(size_t)src * 3 + 1], az = pos[(size_t)src * 3 + 2];
        float bx = pos[(size_t)dst * 3 + 0], by = pos[(size_t)dst * 3 + 1], bz = pos[(size_t)dst * 3 + 2];
        float dx = bx - ax, dy = by - ay, dz = bz - az;
        float dist = sqrtf(fmaf(dx, dx, fmaf(dy, dy, dz * dz)));
        t = fminf(dist, TAB_MAXD) * INV_STEP;
    }
    src = __shfl_sync(0xffffffffu, src, 0, 16);
    dst = __shfl_sync(0xffffffffu, dst, 0, 16);
    t   = __shfl_sync(0xffffffffu, t,   0, 16);
    if (!valid) return;

    int i0 = (int)t;
    i0 = min(i0, TAB_INTERVALS - 1);
    float frac = t - (float)i0;

    const float4* tr = reinterpret_cast<const float4*>(g_tab) + (size_t)i0 * 16 + sub;
    float4 w0 = tr[0];
    float4 w1 = tr[16];
    float4 w;
    w.x = fmaf(frac, w1.x - w0.x, w0.x);
    w.y = fmaf(frac, w1.y - w0.y, w0.y);
    w.z = fmaf(frac, w1.z - w0.z, w0.z);
    w.w = fmaf(frac, w1.w - w0.w, w0.w);

    float4 h = reinterpret_cast<const float4*>(g_h1)[(size_t)src * 16 + sub];
    float mx = h.x * w.x, my = h.y * w.y, mz = h.z * w.z, mw = h.w * w.w;

    float* ap = g_agg + (size_t)dst * F + sub * 4;
    unsigned long long gap = __cvta_generic_to_global(ap);
    asm volatile("red.global.add.v4.f32 [%0], {%1,%2,%3,%4};"
                 :: "l"(gap), "f"(mx), "f"(my), "f"(mz), "f"(mw) : "memory");
}

// ===========================================================================
// Kernel 5 (wmma tf32): fused tail, persistent, 4 warps, 64-row tiles.
// Each warp owns a private 16-row strip -> no __syncthreads in the loop.
//   D1 = agg @ wA ; h2 = ssp(D1+bA)
//   D2 = h2  @ wB ; h3 = D2+bB
//   D3 = h3  @ wC ; out = x + relu(D3+bC)
// wB/wC in smem (pre-rounded tf32, ld=136); wA B-frags from global (L1).
// ===========================================================================
#define WLD 136
#define TS_WB 0
#define TS_WC (DIM * WLD)
#define TS_B0 (2 * DIM * WLD)
#define TS_B1 (2 * DIM * WLD + 64 * WLD)
#define TAIL_SMEM_FLOATS (2 * DIM * WLD + 2 * 64 * WLD)
#define TAIL_SMEM_BYTES (TAIL_SMEM_FLOATS * 4)

__global__ void __launch_bounds__(128, 1)
tail_wmma_kernel(const float* __restrict__ x,
                 const float* __restrict__ wAg, const float* __restrict__ bA,
                 const float* __restrict__ wBg, const float* __restrict__ bB,
                 const float* __restrict__ wCg, const float* __restrict__ bC,
                 float* __restrict__ out, int N) {
    extern __shared__ float sm[];
    float* wBs  = sm + TS_WB;
    float* wCs  = sm + TS_WC;
    float* buf0 = sm + TS_B0;
    float* buf1 = sm + TS_B1;

    int tid  = threadIdx.x;
    int wid  = tid >> 5;
    int lane = tid & 31;

    for (int i = tid; i < DIM * DIM; i += 128) {
        int k = i >> 7, n = i & 127;
        wBs[k * WLD + n] = rtf(wBg[i]);
        wCs[k * WLD + n] = rtf(wCg[i]);
    }
    __syncthreads();

    float* bp0 = buf0 + wid * 16 * WLD;
    float* bp1 = buf1 + wid * 16 * WLD;
    int ntiles = (N + 63) >> 6;

    for (int tile = blockIdx.x; tile < ntiles; tile += gridDim.x) {
        int r0 = tile * 64 + wid * 16;  // this warp's strip (g_agg padded to NMAX)

        wmma::fragment<wmma::accumulator, 16, 16, 8, float> acc[8];

        // ---- Stage A: [16,64] @ wA[64,128] ----
#pragma unroll
        for (int n = 0; n < 8; n++) wmma::fill_fragment(acc[n], 0.0f);
#pragma unroll 1
        for (int k = 0; k < F; k += 8) {
            wmma::fragment<wmma::matrix_a, 16, 16, 8, wmma::precision::tf32, wmma::row_major> a;
            wmma::load_matrix_sync(a, g_agg + (size_t)r0 * F + k, F);
#pragma unroll
            for (int t = 0; t < a.num_elements; t++) a.x[t] = wmma::__float_to_tf32(a.x[t]);
#pragma unroll
            for (int n = 0; n < 8; n++) {
                wmma::fragment<wmma::matrix_b, 16, 16, 8, wmma::precision::tf32, wmma::row_major> b;
                wmma::load_matrix_sync(b, wAg + (size_t)k * DIM + n * 16, DIM);
#pragma unroll
                for (int t = 0; t < b.num_elements; t++) b.x[t] = wmma::__float_to_tf32(b.x[t]);
                wmma::mma_sync(acc[n], a, b, acc[n]);
            }
        }
#pragma unroll
        for (int n = 0; n < 8; n++)
            wmma::store_matrix_sync(bp0 + n * 16, acc[n], WLD, wmma::mem_row_major);
        __syncwarp();

        // epilogue A: h2 = ssp(v + bA), rounded to tf32, in place
#pragma unroll
        for (int i = 0; i < 16; i++) {
            int pos = i * 32 + lane;          // float4 index in 16x128 strip
            int r = pos >> 5, c4 = (pos & 31) * 4;
            float4* p = (float4*)(bp0 + r * WLD + c4);
            float4 v = *p;
            v.x = rtf(sspf(v.x + __ldg(bA + c4 + 0)));
            v.y = rtf(sspf(v.y + __ldg(bA + c4 + 1)));
            v.z = rtf(sspf(v.z + __ldg(bA + c4 + 2)));
            v.w = rtf(sspf(v.w + __ldg(bA + c4 + 3)));
            *p = v;
        }
        __syncwarp();

        // ---- Stage B: h2[16,128] @ wB[128,128] ----
#pragma unroll
        for (int n = 0; n < 8; n++) wmma::fill_fragment(acc[n], 0.0f);
#pragma unroll 1
        for (int k = 0; k < DIM; k += 8) {
            wmma::fragment<wmma::matrix_a, 16, 16, 8, wmma::precision::tf32, wmma::row_major> a;
            wmma::load_matrix_sync(a, bp0 + k, WLD);
#pragma unroll
            for (int n = 0; n < 8; n++) {
                wmma::fragment<wmma::matrix_b, 16, 16, 8, wmma::precision::tf32, wmma::row_major> b;
                wmma::load_matrix_sync(b, wBs + (size_t)k * WLD + n * 16, WLD);
                wmma::mma_sync(acc[n], a, b, acc[n]);
            }
        }
#pragma unroll
        for (int n = 0; n < 8; n++)
            wmma::store_matrix_sync(bp1 + n * 16, acc[n], WLD, wmma::mem_row_major);
        __syncwarp();

        // epilogue B: h3 = v + bB, rounded
#pragma unroll
        for (int i = 0; i < 16; i++) {
            int pos = i * 32 + lane;
            int r = pos >> 5, c4 = (pos & 31) * 4;
            float4* p = (float4*)(bp1 + r * WLD + c4);
            float4 v = *p;
            v.x = rtf(v.x + __ldg(bB + c4 + 0));
            v.y = rtf(v.y + __ldg(bB + c4 + 1));
            v.z = rtf(v.z + __ldg(bB + c4 + 2));
            v.w = rtf(v.w + __ldg(bB + c4 + 3));
            *p = v;
        }
        __syncwarp();

        // ---- Stage C: h3[16,128] @ wC[128,128] ----
#pragma unroll
        for (int n = 0; n < 8; n++) wmma::fill_fragment(acc[n], 0.0f);
#pragma unroll 1
        for (int k = 0; k < DIM; k += 8) {
            wmma::fragment<wmma::matrix_a, 16, 16, 8, wmma::precision::tf32, wmma::row_major> a;
            wmma::load_matrix_sync(a, bp1 + k, WLD);
#pragma unroll
            for (int n = 0; n < 8; n++) {
                wmma::fragment<wmma::matrix_b, 16, 16, 8, wmma::precision::tf32, wmma::row_major> b;
                wmma::load_matrix_sync(b, wCs + (size_t)k * WLD + n * 16, WLD);
                wmma::mma_sync(acc[n], a, b, acc[n]);
            }
        }
#pragma unroll
        for (int n = 0; n < 8; n++)
            wmma::store_matrix_sync(bp0 + n * 16, acc[n], WLD, wmma::mem_row_major);
        __syncwarp();

        // final epilogue: out = x + relu(v + bC)
#pragma unroll
        for (int i = 0; i < 16; i++) {
            int pos = i * 32 + lane;
            int r = pos >> 5, c4 = (pos & 31) * 4;
            int gr = r0 + r;
            if (gr < N) {
                float4 v  = *(float4*)(bp0 + r * WLD + c4);
                float4 xv = *(const float4*)(x + (size_t)gr * DIM + c4);
                float4 o;
                o.x = xv.x + fmaxf(v.x + __ldg(bC + c4 + 0), 0.f);
                o.y = xv.y + fmaxf(v.y + __ldg(bC + c4 + 1), 0.f);
                o.z = xv.z + fmaxf(v.z + __ldg(bC + c4 + 2), 0.f);
                o.w = xv.w + fmaxf(v.w + __ldg(bC + c4 + 3), 0.f);
                *(float4*)(out + (size_t)gr * DIM + c4) = o;
            }
        }
        __syncwarp();  // strip reuse next tile
    }
}

// ===========================================================================
extern "C" void kernel_launch(void* const* d_in, const int* in_sizes, int n_in,
                              void* d_out, int out_size) {
    const float* x      = (const float*)d_in[0];
    const float* pos    = (const float*)d_in[1];
    const int*   ei     = (const int*)d_in[2];
    const float* mlp_w1 = (const float*)d_in[3];
    const float* mlp_b1 = (const float*)d_in[4];
    const float* mlp_w2 = (const float*)d_in[5];
    const float* mlp_b2 = (const float*)d_in[6];
    const float* clin1w = (const float*)d_in[7];
    const float* clin2w = (const float*)d_in[8];
    const float* clin2b = (const float*)d_in[9];
    const float* intw   = (const float*)d_in[10];
    const float* intb   = (const float*)d_in[11];
    const float* l1w    = (const float*)d_in[12];
    const float* l1b    = (const float*)d_in[13];
    float* out = (float*)d_out;

    int N = in_sizes[0] / DIM;
    int E = in_sizes[2] / 2;

    cudaFuncSetAttribute(tail_wmma_kernel, cudaFuncAttributeMaxDynamicSharedMemorySize,
                         TAIL_SMEM_BYTES);

    table_kernel<<<TAB_ROWS, 64>>>(mlp_w1, mlp_b1, mlp_w2, mlp_b2);

    int n4 = N * 16;
    zero_agg_kernel<<<(n4 + 255) / 256, 256>>>(n4);

    int nstrips = (N + 15) / 16;
    gemm1_wmma_kernel<<<(nstrips + 7) / 8, 256>>>(x, clin1w, N);

    long long eblocks = ((long long)E + 15) / 16;
    edge_kernel<<<(unsigned)eblocks, 256>>>(ei, pos, E);

    tail_wmma_kernel<<<148, 128, TAIL_SMEM_BYTES>>>(x, clin2w, clin2b, intw, intb,
                                                    l1w, l1b, out, N);
}

// round 6
// speedup vs baseline: 1.5257x; 1.5257x over previous
#include <cuda_runtime.h>
#include <cuda_fp16.h>
#include <mma.h>
#include <math.h>
#include <stdint.h>

using namespace nvcuda;

#define DIM 128
#define F 64
#define NG 50
#define NMAX 100352

#define TAB_INTERVALS 8192
#define TAB_ROWS (TAB_INTERVALS + 1)
#define TAB_MAXD 13.0f

static __device__ __align__(16) __half g_tabh[(size_t)TAB_ROWS * F + 64];
static __device__ __align__(16) __half g_h1[(size_t)NMAX * F];
static __device__ __align__(16) float  g_agg[(size_t)NMAX * F];
static __device__ __align__(16) __half g_w1h[DIM * F];
static __device__ __align__(16) __half g_wAh[F * DIM];
static __device__ __align__(16) __half g_wBh[DIM * DIM];
static __device__ __align__(16) __half g_wCh[DIM * DIM];

__device__ __forceinline__ float sspf(float v) {
    return fmaxf(v, 0.0f) + log1pf(expf(-fabsf(v))) - 0.69314718055994531f;
}

// ===========================================================================
// Kernel 0: convert weights to fp16
// ===========================================================================
__global__ void prep_weights(const float* __restrict__ w1, const float* __restrict__ wA,
                             const float* __restrict__ wB, const float* __restrict__ wC) {
    int i = blockIdx.x * 256 + threadIdx.x;
    if (i < DIM * F)  g_w1h[i] = __float2half(w1[i]);
    if (i < F * DIM)  g_wAh[i] = __float2half(wA[i]);
    if (i < DIM * DIM) {
        g_wBh[i] = __float2half(wB[i]);
        g_wCh[i] = __float2half(wC[i]);
    }
}

// ===========================================================================
// Kernel 1: dist -> W*C table (fp16 output)
// ===========================================================================
__global__ void table_kernel(const float* __restrict__ w1, const float* __restrict__ b1,
                             const float* __restrict__ w2, const float* __restrict__ b2) {
    __shared__ float gauss[NG];
    __shared__ float hid[F];
    int e = blockIdx.x;
    int f = threadIdx.x;  // 0..63
    float dist = (float)e * (TAB_MAXD / (float)TAB_INTERVALS);

    const float dOff  = 10.0f / 49.0f;
    const float coeff = -0.5f / (dOff * dOff);

    if (f < NG) {
        float d = dist - (float)f * dOff;
        gauss[f] = expf(coeff * d * d);
    }
    __syncthreads();

    float pre = b1[f];
#pragma unroll 1
    for (int i = 0; i < NG; i++) pre = fmaf(gauss[i], w1[i * F + f], pre);
    hid[f] = sspf(pre);
    __syncthreads();

    float o = b2[f];
#pragma unroll 1
    for (int i = 0; i < F; i++) o = fmaf(hid[i], w2[i * F + f], o);

    float C = 0.5f * (cosf(dist * (float)(M_PI / 10.0)) + 1.0f);
    g_tabh[(size_t)e * F + f] = __float2half(o * C);
}

// ===========================================================================
// Kernel 2: zero agg (fp32)
// ===========================================================================
__global__ void zero_agg_kernel(int n4) {
    int i = blockIdx.x * blockDim.x + threadIdx.x;
    if (i < n4) reinterpret_cast<float4*>(g_agg)[i] = make_float4(0.f, 0.f, 0.f, 0.f);
}

// ===========================================================================
// Kernel 3 (wmma fp16): h1 = x @ conv_lin1_w  [N,128]@[128,64] -> half
// 256 threads, 128-row tiles, 8 warps x 16-row private strips.
// ===========================================================================
#define G1_SMEM_BYTES (128*136*2 + 128*72*2 + 8*16*72*4)

__global__ void __launch_bounds__(256)
gemm1_h_kernel(const float* __restrict__ x, int N) {
    extern __shared__ char smraw[];
    __half* xs = (__half*)smraw;                       // [128][136]
    __half* ws = xs + 128 * 136;                       // [128][72]
    float*  scr = (float*)(ws + 128 * 72);             // 8 x [16][72]

    int tid = threadIdx.x, wid = tid >> 5, lane = tid & 31;
    int row0 = blockIdx.x * 128;

    for (int i = tid; i < DIM * F; i += 256) {
        int k = i >> 6, n = i & 63;
        ws[k * 72 + n] = g_w1h[i];
    }
    for (int i = tid; i < 128 * 32; i += 256) {        // float4 granules
        int r = i >> 5, c4 = (i & 31) * 4;
        int gr = row0 + r;
        float4 v = (gr < N) ? *(const float4*)(x + (size_t)gr * DIM + c4)
                            : make_float4(0.f, 0.f, 0.f, 0.f);
        __half2* p = (__half2*)(xs + r * 136 + c4);
        p[0] = __floats2half2_rn(v.x, v.y);
        p[1] = __floats2half2_rn(v.z, v.w);
    }
    __syncthreads();

    int sr = wid * 16;
    wmma::fragment<wmma::accumulator, 16, 16, 16, float> acc[4];
#pragma unroll
    for (int n = 0; n < 4; n++) wmma::fill_fragment(acc[n], 0.0f);
#pragma unroll
    for (int k = 0; k < 8; k++) {
        wmma::fragment<wmma::matrix_a, 16, 16, 16, __half, wmma::row_major> a;
        wmma::load_matrix_sync(a, xs + sr * 136 + k * 16, 136);
#pragma unroll
        for (int n = 0; n < 4; n++) {
            wmma::fragment<wmma::matrix_b, 16, 16, 16, __half, wmma::row_major> b;
            wmma::load_matrix_sync(b, ws + (k * 16) * 72 + n * 16, 72);
            wmma::mma_sync(acc[n], a, b, acc[n]);
        }
    }
    float* sw = scr + wid * 16 * 72;
#pragma unroll
    for (int n = 0; n < 4; n++)
        wmma::store_matrix_sync(sw + n * 16, acc[n], 72, wmma::mem_row_major);
    __syncwarp();

#pragma unroll
    for (int r = 0; r < 16; r++) {
        int gr = row0 + sr + r;
        if (gr < N) {
            int c2 = lane * 2;
            __half2 hv = __floats2half2_rn(sw[r * 72 + c2], sw[r * 72 + c2 + 1]);
            *(__half2*)(&g_h1[(size_t)gr * F + c2]) = hv;
        }
    }
}

// ===========================================================================
// Kernel 4: edge scatter. 16 lanes/edge, fp16 tab + fp16 h1, fp32 v4 RED.
// ===========================================================================
__global__ void edge_kernel(const int* __restrict__ ei,
                            const float* __restrict__ pos, int E) {
    const float INV_STEP = (float)TAB_INTERVALS / TAB_MAXD;
    int lane = threadIdx.x & 31;
    int sub  = lane & 15;
    long long widx = (long long)blockIdx.x * (blockDim.x >> 5) + (threadIdx.x >> 5);
    long long e = widx * 2 + (lane >> 4);
    bool valid = (e < E);

    int src = 0, dst = 0;
    float t = 0.f;
    if (sub == 0 && valid) {
        src = ei[e];
        dst = ei[E + e];
        float ax = pos[(size_t)src * 3 + 0], ay = pos[(size_t)src * 3 + 1], az = pos[(size_t)src * 3 + 2];
        float bx = pos[(size_t)dst * 3 + 0], by = pos[(size_t)dst * 3 + 1], bz = pos[(size_t)dst * 3 + 2];
        float dx = bx - ax, dy = by - ay, dz = bz - az;
        float dist = sqrtf(fmaf(dx, dx, fmaf(dy, dy, dz * dz)));
        t = fminf(dist, TAB_MAXD) * INV_STEP;
    }
    src = __shfl_sync(0xffffffffu, src, 0, 16);
    dst = __shfl_sync(0xffffffffu, dst, 0, 16);
    t   = __shfl_sync(0xffffffffu, t,   0, 16);
    if (!valid) return;

    int i0 = (int)t;
    i0 = min(i0, TAB_INTERVALS - 1);
    float frac = t - (float)i0;

    const __half* tp = g_tabh + (size_t)i0 * F + sub * 4;
    uint2 r0 = *(const uint2*)tp;
    uint2 r1 = *(const uint2*)(tp + F);
    __half2 a0 = *(__half2*)&r0.x, a1 = *(__half2*)&r0.y;
    __half2 b0 = *(__half2*)&r1.x, b1 = *(__half2*)&r1.y;
    float2 w00 = __half22float2(a0), w01 = __half22float2(a1);
    float2 w10 = __half22float2(b0), w11 = __half22float2(b1);
    float wx = fmaf(frac, w10.x - w00.x, w00.x);
    float wy = fmaf(frac, w10.y - w00.y, w00.y);
    float wz = fmaf(frac, w11.x - w01.x, w01.x);
    float ww = fmaf(frac, w11.y - w01.y, w01.y);

    uint2 hr = *(const uint2*)(g_h1 + (size_t)src * F + sub * 4);
    float2 h0 = __half22float2(*(__half2*)&hr.x);
    float2 h1v = __half22float2(*(__half2*)&hr.y);

    float mx = h0.x * wx, my = h0.y * wy, mz = h1v.x * wz, mw = h1v.y * ww;

    float* ap = g_agg + (size_t)dst * F + sub * 4;
    unsigned long long gap = __cvta_generic_to_global(ap);
    asm volatile("red.global.add.v4.f32 [%0], {%1,%2,%3,%4};"
                 :: "l"(gap), "f"(mx), "f"(my), "f"(mz), "f"(mw) : "memory");
}

// ===========================================================================
// Kernel 5 (wmma fp16): fused tail. 256 threads, 128-row tiles,
// 8 warps with private 16-row strips (no block sync inside stages).
// ===========================================================================
#define SCRLD 132
#define TOFF_WA 0
#define TOFF_WB (TOFF_WA + 64*136*2)
#define TOFF_WC (TOFF_WB + 128*136*2)
#define TOFF_ACT (TOFF_WC + 128*136*2)
#define TOFF_SCR (TOFF_ACT + 128*136*2)
#define TOFF_BIAS (TOFF_SCR + 8*16*SCRLD*4)
#define TAIL_SMEM_BYTES (TOFF_BIAS + 3*128*4)

__global__ void __launch_bounds__(256)
tail_h_kernel(const float* __restrict__ x,
              const float* __restrict__ bA, const float* __restrict__ bB,
              const float* __restrict__ bC,
              float* __restrict__ out, int N) {
    extern __shared__ char smraw[];
    __half* wAs = (__half*)(smraw + TOFF_WA);
    __half* wBs = (__half*)(smraw + TOFF_WB);
    __half* wCs = (__half*)(smraw + TOFF_WC);
    __half* act = (__half*)(smraw + TOFF_ACT);
    float*  scr = (float*)(smraw + TOFF_SCR);
    float*  bias = (float*)(smraw + TOFF_BIAS);

    int tid = threadIdx.x, wid = tid >> 5, lane = tid & 31;
    int row0 = blockIdx.x * 128;

    for (int i = tid; i < F * DIM; i += 256) {
        int k = i >> 7, n = i & 127;
        wAs[k * 136 + n] = g_wAh[i];
    }
    for (int i = tid; i < DIM * DIM; i += 256) {
        int k = i >> 7, n = i & 127;
        wBs[k * 136 + n] = g_wBh[i];
        wCs[k * 136 + n] = g_wCh[i];
    }
    if (tid < 128) {
        bias[tid]       = bA[tid];
        bias[128 + tid] = bB[tid];
        bias[256 + tid] = bC[tid];
    }
    // agg tile [128][64] fp32 -> act (half) cols 0..63
    for (int i = tid; i < 128 * 16; i += 256) {
        int r = i >> 4, c4 = (i & 15) * 4;
        int gr = row0 + r;
        float4 v = (gr < N) ? *(const float4*)(g_agg + (size_t)gr * F + c4)
                            : make_float4(0.f, 0.f, 0.f, 0.f);
        __half2* p = (__half2*)(act + r * 136 + c4);
        p[0] = __floats2half2_rn(v.x, v.y);
        p[1] = __floats2half2_rn(v.z, v.w);
    }
    __syncthreads();

    int sr = wid * 16;
    float* sw = scr + wid * 16 * SCRLD;
    wmma::fragment<wmma::accumulator, 16, 16, 16, float> acc[8];

    // ---- Stage A: [16,64] @ wA[64,128] ----
#pragma unroll
    for (int n = 0; n < 8; n++) wmma::fill_fragment(acc[n], 0.0f);
#pragma unroll
    for (int k = 0; k < 4; k++) {
        wmma::fragment<wmma::matrix_a, 16, 16, 16, __half, wmma::row_major> a;
        wmma::load_matrix_sync(a, act + sr * 136 + k * 16, 136);
#pragma unroll
        for (int n = 0; n < 8; n++) {
            wmma::fragment<wmma::matrix_b, 16, 16, 16, __half, wmma::row_major> b;
            wmma::load_matrix_sync(b, wAs + (k * 16) * 136 + n * 16, 136);
            wmma::mma_sync(acc[n], a, b, acc[n]);
        }
    }
#pragma unroll
    for (int n = 0; n < 8; n++)
        wmma::store_matrix_sync(sw + n * 16, acc[n], SCRLD, wmma::mem_row_major);
    __syncwarp();
    // epi A: h2 = ssp(v+bA) -> act strip (half)
#pragma unroll
    for (int r = 0; r < 16; r++) {
        int c4 = lane * 4;
        float4 v = *(float4*)(sw + r * SCRLD + c4);
        v.x = sspf(v.x + bias[c4 + 0]);
        v.y = sspf(v.y + bias[c4 + 1]);
        v.z = sspf(v.z + bias[c4 + 2]);
        v.w = sspf(v.w + bias[c4 + 3]);
        __half2* p = (__half2*)(act + (sr + r) * 136 + c4);
        p[0] = __floats2half2_rn(v.x, v.y);
        p[1] = __floats2half2_rn(v.z, v.w);
    }
    __syncwarp();

    // ---- Stage B: h2[16,128] @ wB ----
#pragma unroll
    for (int n = 0; n < 8; n++) wmma::fill_fragment(acc[n], 0.0f);
#pragma unroll
    for (int k = 0; k < 8; k++) {
        wmma::fragment<wmma::matrix_a, 16, 16, 16, __half, wmma::row_major> a;
        wmma::load_matrix_sync(a, act + sr * 136 + k * 16, 136);
#pragma unroll
        for (int n = 0; n < 8; n++) {
            wmma::fragment<wmma::matrix_b, 16, 16, 16, __half, wmma::row_major> b;
            wmma::load_matrix_sync(b, wBs + (k * 16) * 136 + n * 16, 136);
            wmma::mma_sync(acc[n], a, b, acc[n]);
        }
    }
#pragma unroll
    for (int n = 0; n < 8; n++)
        wmma::store_matrix_sync(sw + n * 16, acc[n], SCRLD, wmma::mem_row_major);
    __syncwarp();
    // epi B: h3 = v + bB -> act strip
#pragma unroll
    for (int r = 0; r < 16; r++) {
        int c4 = lane * 4;
        float4 v = *(float4*)(sw + r * SCRLD + c4);
        v.x += bias[128 + c4 + 0];
        v.y += bias[128 + c4 + 1];
        v.z += bias[128 + c4 + 2];
        v.w += bias[128 + c4 + 3];
        __half2* p = (__half2*)(act + (sr + r) * 136 + c4);
        p[0] = __floats2half2_rn(v.x, v.y);
        p[1] = __floats2half2_rn(v.z, v.w);
    }
    __syncwarp();

    // ---- Stage C: h3[16,128] @ wC ----
#pragma unroll
    for (int n = 0; n < 8; n++) wmma::fill_fragment(acc[n], 0.0f);
#pragma unroll
    for (int k = 0; k < 8; k++) {
        wmma::fragment<wmma::matrix_a, 16, 16, 16, __half, wmma::row_major> a;
        wmma::load_matrix_sync(a, act + sr * 136 + k * 16, 136);
#pragma unroll
        for (int n = 0; n < 8; n++) {
            wmma::fragment<wmma::matrix_b, 16, 16, 16, __half, wmma::row_major> b;
            wmma::load_matrix_sync(b, wCs + (k * 16) * 136 + n * 16, 136);
            wmma::mma_sync(acc[n], a, b, acc[n]);
        }
    }
#pragma unroll
    for (int n = 0; n < 8; n++)
        wmma::store_matrix_sync(sw + n * 16, acc[n], SCRLD, wmma::mem_row_major);
    __syncwarp();
    // final: out = x + relu(v + bC)
#pragma unroll
    for (int r = 0; r < 16; r++) {
        int gr = row0 + sr + r;
        if (gr < N) {
            int c4 = lane * 4;
            float4 v  = *(float4*)(sw + r * SCRLD + c4);
            float4 xv = *(const float4*)(x + (size_t)gr * DIM + c4);
            float4 o;
            o.x = xv.x + fmaxf(v.x + bias[256 + c4 + 0], 0.f);
            o.y = xv.y + fmaxf(v.y + bias[256 + c4 + 1], 0.f);
            o.z = xv.z + fmaxf(v.z + bias[256 + c4 + 2], 0.f);
            o.w = xv.w + fmaxf(v.w + bias[256 + c4 + 3], 0.f);
            *(float4*)(out + (size_t)gr * DIM + c4) = o;
        }
    }
}

// ===========================================================================
extern "C" void kernel_launch(void* const* d_in, const int* in_sizes, int n_in,
                              void* d_out, int out_size) {
    const float* x      = (const float*)d_in[0];
    const float* pos    = (const float*)d_in[1];
    const int*   ei     = (const int*)d_in[2];
    const float* mlp_w1 = (const float*)d_in[3];
    const float* mlp_b1 = (const float*)d_in[4];
    const float* mlp_w2 = (const float*)d_in[5];
    const float* mlp_b2 = (const float*)d_in[6];
    const float* clin1w = (const float*)d_in[7];
    const float* clin2w = (const float*)d_in[8];
    const float* clin2b = (const float*)d_in[9];
    const float* intw   = (const float*)d_in[10];
    const float* intb   = (const float*)d_in[11];
    const float* l1w    = (const float*)d_in[12];
    const float* l1b    = (const float*)d_in[13];
    float* out = (float*)d_out;

    int N = in_sizes[0] / DIM;
    int E = in_sizes[2] / 2;

    cudaFuncSetAttribute(gemm1_h_kernel, cudaFuncAttributeMaxDynamicSharedMemorySize,
                         G1_SMEM_BYTES);
    cudaFuncSetAttribute(tail_h_kernel, cudaFuncAttributeMaxDynamicSharedMemorySize,
                         TAIL_SMEM_BYTES);

    prep_weights<<<(DIM * DIM + 255) / 256, 256>>>(clin1w, clin2w, intw, l1w);
    table_kernel<<<TAB_ROWS, 64>>>(mlp_w1, mlp_b1, mlp_w2, mlp_b2);

    int n4 = N * 16;
    zero_agg_kernel<<<(n4 + 255) / 256, 256>>>(n4);

    int ntiles = (N + 127) / 128;
    gemm1_h_kernel<<<ntiles, 256, G1_SMEM_BYTES>>>(x, N);

    long long eblocks = ((long long)E + 15) / 16;
    edge_kernel<<<(unsigned)eblocks, 256>>>(ei, pos, E);

    tail_h_kernel<<<ntiles, 256, TAIL_SMEM_BYTES>>>(x, clin2b, intb, l1b, out, N);
}